// round 15
// baseline (speedup 1.0000x reference)
#include <cuda_runtime.h>
#include <cuda_bf16.h>
#include <math.h>
#include <stdint.h>

#define Bc 4
#define Cc 512
#define Tc 8
#define Lc 512
#define Hc 8
#define HD 64
#define BT 32               // B*T
#define CTL (Cc*Tc*Lc)
#define TL  (Tc*Lc)
#define SAP 20              // GEMM smem word pitch for row-major bf16x2 tiles
#define XP  68              // K-major A tile word pitch (conflict-free trans-LDSM)
#define BSTR 2560           // B buffer stride (words)  = 128*SAP
#define XSTR 2176           // X buffer stride (words)  = 32*XP
#define ASTR 2560           // A buffer stride (words)
#define ATTN_SMEM 55296     // 18432 (Q) + 2*9216 (K) + 2*9216 (V^T)

// ---------------- scratch (device globals; no allocation allowed) ----------
__device__ __align__(16) float g_pooled[BT*Cc];
__device__ __align__(16) float g_h1   [BT*Cc];
__device__ __align__(16) float g_gw   [BT*Hc];
__device__ __align__(16) unsigned short g_qh[(size_t)BT*Hc*Lc*HD];  // bf16, 0.125 folded
__device__ __align__(16) unsigned short g_kh[(size_t)BT*Hc*Lc*HD];  // bf16
__device__ __align__(16) unsigned short g_vh[(size_t)BT*Hc*Lc*HD];  // bf16, gw folded
__device__ __align__(16) unsigned short g_oh[(size_t)BT*Lc*Cc];     // bf16 attn out

// ---------------- helpers ---------------------------------------------------
__device__ __forceinline__ void mma_bf16(float c[4], const uint32_t a[4],
                                         uint32_t b0, uint32_t b1) {
    asm volatile(
        "mma.sync.aligned.m16n8k16.row.col.f32.bf16.bf16.f32 "
        "{%0,%1,%2,%3},{%4,%5,%6,%7},{%8,%9},{%0,%1,%2,%3};"
        : "+f"(c[0]), "+f"(c[1]), "+f"(c[2]), "+f"(c[3])
        : "r"(a[0]), "r"(a[1]), "r"(a[2]), "r"(a[3]), "r"(b0), "r"(b1));
}
__device__ __forceinline__ uint32_t packbf(float lo, float hi) {
    uint32_t r;
    asm("cvt.rn.bf16x2.f32 %0, %1, %2;" : "=r"(r) : "f"(hi), "f"(lo));
    return r;
}
__device__ __forceinline__ void ldsm4(uint32_t a[4], uint32_t addr) {
    asm volatile("ldmatrix.sync.aligned.m8n8.x4.shared.b16 {%0,%1,%2,%3}, [%4];"
        : "=r"(a[0]), "=r"(a[1]), "=r"(a[2]), "=r"(a[3]) : "r"(addr));
}
__device__ __forceinline__ void ldsm4t(uint32_t a[4], uint32_t addr) {
    asm volatile("ldmatrix.sync.aligned.m8n8.x4.trans.shared.b16 {%0,%1,%2,%3}, [%4];"
        : "=r"(a[0]), "=r"(a[1]), "=r"(a[2]), "=r"(a[3]) : "r"(addr));
}
__device__ __forceinline__ uint32_t smem_u32(const void* p) {
    return (uint32_t)__cvta_generic_to_shared(p);
}

// ---------------- pooled[bt,c] = mean_l e[b,c,t,l] --------------------------
__global__ void k_pool(const float* __restrict__ e) {
    int w    = (blockIdx.x * blockDim.x + threadIdx.x) >> 5;
    int lane = threadIdx.x & 31;
    if (w >= BT*Cc) return;
    int bt = w / Cc, c = w % Cc;
    int b = bt / Tc, t = bt % Tc;
    const float* p = e + (size_t)b*CTL + (size_t)c*TL + (size_t)t*Lc;
    float s = 0.f;
    #pragma unroll 4
    for (int l = lane; l < Lc; l += 32) s += p[l];
    #pragma unroll
    for (int o = 16; o; o >>= 1) s += __shfl_xor_sync(0xffffffffu, s, o);
    if (!lane) g_pooled[w] = s * (1.0f/Lc);
}

// ---------------- gate layer 1 ---------------------------------------------
__global__ void __launch_bounds__(256) k_gate1(
        const float* __restrict__ Wg1, const float* __restrict__ bg1) {
    __shared__ float sp[Cc];
    int bt = blockIdx.y;
    int r0 = blockIdx.x * 128;
    int tid = threadIdx.x, warp = tid >> 5, lane = tid & 31;
    sp[tid] = g_pooled[bt*Cc + tid];
    sp[tid+256] = g_pooled[bt*Cc + tid + 256];
    __syncthreads();
    const float4* pp = (const float4*)sp;
    #pragma unroll
    for (int i = 0; i < 16; ++i) {
        int r = r0 + warp*16 + i;
        const float4* wr = (const float4*)(Wg1 + (size_t)r*Cc);
        float a = 0.f;
        #pragma unroll
        for (int k = lane; k < Cc/4; k += 32) {
            float4 wv = wr[k]; float4 pv = pp[k];
            a += wv.x*pv.x + wv.y*pv.y + wv.z*pv.z + wv.w*pv.w;
        }
        #pragma unroll
        for (int o = 16; o; o >>= 1) a += __shfl_xor_sync(0xffffffffu, a, o);
        if (!lane) g_h1[bt*Cc + r] = tanhf(a + bg1[r]);
    }
}

// ---------------- gate layer 2 + softmax ------------------------------------
__global__ void __launch_bounds__(256) k_gate2(
        const float* __restrict__ Wg2, const float* __restrict__ bg2) {
    __shared__ float sg[Hc];
    int bt = blockIdx.x;
    int tid = threadIdx.x, warp = tid >> 5, lane = tid & 31;
    if (warp < Hc) {
        const float4* w2 = (const float4*)(Wg2 + (size_t)warp*Cc);
        const float4* hp = (const float4*)(g_h1 + bt*Cc);
        float a = 0.f;
        #pragma unroll
        for (int k = lane; k < Cc/4; k += 32) {
            float4 wv = w2[k]; float4 hv = hp[k];
            a += wv.x*hv.x + wv.y*hv.y + wv.z*hv.z + wv.w*hv.w;
        }
        #pragma unroll
        for (int o = 16; o; o >>= 1) a += __shfl_xor_sync(0xffffffffu, a, o);
        if (!lane) sg[warp] = a + bg2[warp];
    }
    __syncthreads();
    if (tid == 0) {
        float mx = sg[0];
        #pragma unroll
        for (int h = 1; h < Hc; ++h) mx = fmaxf(mx, sg[h]);
        float ex[Hc], ssum = 0.f;
        #pragma unroll
        for (int h = 0; h < Hc; ++h) { ex[h] = expf(sg[h]-mx); ssum += ex[h]; }
        #pragma unroll
        for (int h = 0; h < Hc; ++h) g_gw[bt*Hc+h] = ex[h]/ssum;
    }
}

// ---------------- bf16 tensor-core GEMM (double-buffered smem) --------------
// which 0: A = e slab (K-major, ldsm.trans), fused q-norm -> g_qh
// which 1: A = x slab (K-major, ldsm.trans), fused k/v-norm -> g_kh/g_vh
// which 2: A = g_oh (bf16 row-major),       fused residual+transpose -> out
__global__ void __launch_bounds__(256, 2) k_gemm_bf16(int which,
        const float* __restrict__ W, const float* __restrict__ bias,
        const float* __restrict__ src, float* __restrict__ outp) {
    __shared__ __align__(16) uint32_t smw[10240];       // 40960 bytes
    uint32_t* sBw = smw;                                // [2][128*SAP]
    uint32_t* sXw = smw + 2*BSTR;                       // [2][32*XP]   (which<2)
    uint32_t* sAw = smw + 2*BSTR;                       // [2][128*SAP] (which==2)
    float*    stage = (float*)smw;                      // epilogue alias (which==2)

    int bt = blockIdx.z;
    int b = bt / Tc, t = bt % Tc;
    int m0 = blockIdx.y * 128;
    int n0 = blockIdx.x * 128;
    int tid = threadIdx.x, lane = tid & 31, wid = tid >> 5;
    int wm = (wid & 3) * 32;
    int wn = (wid >> 2) * 64;
    int r8 = tid >> 3;            // 0..31
    int c8 = (tid & 7) * 4;

    const float* tb = src + (size_t)b*CTL + (size_t)t*Lc;       // which<2
    const uint32_t* Ao = (const uint32_t*)g_oh + (size_t)bt*Lc*(Cc/2); // which==2

    // LDSM base addresses (buffer 0)
    uint32_t adB = smem_u32(sBw) + ((((wn + (lane & 7) + ((lane >> 4) << 3))*SAP)
                                     + (((lane >> 3) & 1) << 2)) << 2);
    uint32_t adA = smem_u32(sAw) + ((((wm + (lane & 15))*SAP) + ((lane >> 4) << 2)) << 2);
    uint32_t adX = smem_u32(sXw)
        + ((((lane & 7) + ((lane >> 4) << 3))*XP + (wm >> 1) + (((lane >> 3) & 1) << 2)) << 2);

    float acc[2][8][4] = {};
    float4 pB[4];
    float4 pA[4];
    uint4  qA[2];

    // ---- load tile 0 into regs ----
    #pragma unroll
    for (int i = 0; i < 4; ++i)
        pB[i] = *(const float4*)(W + (size_t)(n0 + r8 + i*32)*Cc + c8);
    if (which == 2) {
        const uint32_t* ap = Ao + (size_t)(tid >> 1)*(Cc/2) + (tid & 1)*8;
        qA[0] = *(const uint4*)(ap);
        qA[1] = *(const uint4*)(ap + 4);
    } else {
        #pragma unroll
        for (int i = 0; i < 4; ++i)
            pA[i] = *(const float4*)(tb + (size_t)r8*TL + m0 + (tid & 7)*16 + 4*i);
    }
    // ---- store tile 0 -> buffer 0 ----
    #pragma unroll
    for (int i = 0; i < 4; ++i) {
        uint2 u = make_uint2(packbf(pB[i].x, pB[i].y), packbf(pB[i].z, pB[i].w));
        *(uint2*)&sBw[(r8 + i*32)*SAP + (c8 >> 1)] = u;
    }
    if (which == 2) {
        uint32_t* dp = &sAw[(tid >> 1)*SAP + (tid & 1)*8];
        *(uint4*)dp       = qA[0];
        *(uint4*)(dp + 4) = qA[1];
    } else {
        uint32_t* dp = &sXw[r8*XP + (tid & 7)*8];
        #pragma unroll
        for (int i = 0; i < 4; ++i)
            *(uint2*)(dp + 2*i) =
                make_uint2(packbf(pA[i].x, pA[i].y), packbf(pA[i].z, pA[i].w));
    }
    // ---- prefetch tile 1 into regs ----
    #pragma unroll
    for (int i = 0; i < 4; ++i)
        pB[i] = *(const float4*)(W + (size_t)(n0 + r8 + i*32)*Cc + 32 + c8);
    if (which == 2) {
        const uint32_t* ap = Ao + (size_t)(tid >> 1)*(Cc/2) + 16 + (tid & 1)*8;
        qA[0] = *(const uint4*)(ap);
        qA[1] = *(const uint4*)(ap + 4);
    } else {
        #pragma unroll
        for (int i = 0; i < 4; ++i)
            pA[i] = *(const float4*)(tb + (size_t)(32 + r8)*TL + m0 + (tid & 7)*16 + 4*i);
    }
    __syncthreads();

    // ---- main loop: 16 k-tiles, ping-pong, ONE sync per tile ----
    for (int kt = 0; kt < 16; ++kt) {
        int cur = kt & 1, nxt = cur ^ 1;
        if (kt < 15) {
            // store tile kt+1 (in regs) -> buffer nxt
            #pragma unroll
            for (int i = 0; i < 4; ++i) {
                uint2 u = make_uint2(packbf(pB[i].x, pB[i].y), packbf(pB[i].z, pB[i].w));
                *(uint2*)&sBw[nxt*BSTR + (r8 + i*32)*SAP + (c8 >> 1)] = u;
            }
            if (which == 2) {
                uint32_t* dp = &sAw[nxt*ASTR + (tid >> 1)*SAP + (tid & 1)*8];
                *(uint4*)dp       = qA[0];
                *(uint4*)(dp + 4) = qA[1];
            } else {
                uint32_t* dp = &sXw[nxt*XSTR + r8*XP + (tid & 7)*8];
                #pragma unroll
                for (int i = 0; i < 4; ++i)
                    *(uint2*)(dp + 2*i) =
                        make_uint2(packbf(pA[i].x, pA[i].y), packbf(pA[i].z, pA[i].w));
            }
        }
        if (kt < 14) {
            // prefetch tile kt+2 into regs
            int kn = (kt + 2) * 32;
            #pragma unroll
            for (int i = 0; i < 4; ++i)
                pB[i] = *(const float4*)(W + (size_t)(n0 + r8 + i*32)*Cc + kn + c8);
            if (which == 2) {
                const uint32_t* ap = Ao + (size_t)(tid >> 1)*(Cc/2) + (kn >> 1) + (tid & 1)*8;
                qA[0] = *(const uint4*)(ap);
                qA[1] = *(const uint4*)(ap + 4);
            } else {
                #pragma unroll
                for (int i = 0; i < 4; ++i)
                    pA[i] = *(const float4*)(tb + (size_t)(kn + r8)*TL + m0 + (tid & 7)*16 + 4*i);
            }
        }
        // mma from buffer cur
        uint32_t bofB = cur * (BSTR*4);
        uint32_t bofX = cur * (XSTR*4);
        #pragma unroll
        for (int ks = 0; ks < 2; ++ks) {
            uint32_t A0[4], A1[4];
            if (which == 2) {
                ldsm4(A0, adA + bofB + ((ks*8) << 2));
                ldsm4(A1, adA + bofB + ((16*SAP + ks*8) << 2));
            } else {
                ldsm4t(A0, adX + bofX + ((ks*16*XP) << 2));
                ldsm4t(A1, adX + bofX + ((ks*16*XP + 8) << 2));
            }
            #pragma unroll
            for (int jp = 0; jp < 4; ++jp) {
                uint32_t bb[4];
                ldsm4(bb, adB + bofB + ((jp*16*SAP + ks*8) << 2));
                mma_bf16(acc[0][2*jp],   A0, bb[0], bb[1]);
                mma_bf16(acc[1][2*jp],   A1, bb[0], bb[1]);
                mma_bf16(acc[0][2*jp+1], A0, bb[2], bb[3]);
                mma_bf16(acc[1][2*jp+1], A1, bb[2], bb[3]);
            }
        }
        __syncthreads();
    }

    int row = lane >> 2, col = (lane & 3) * 2;
    if (which < 2) {
        // fused normalization epilogue (head = 64 cols = one warp tile column)
        int g = (n0 + wn) >> 6;
        float bb0[8], bb1[8];
        #pragma unroll
        for (int j = 0; j < 8; ++j) {
            int gn = n0 + wn + j*8 + col;
            bb0[j] = bias[gn]; bb1[j] = bias[gn+1];
        }
        unsigned short* dst; float gmul;
        if (which == 0)      { dst = g_qh + ((size_t)(bt*Hc + g))*Lc*HD; gmul = 0.125f; }
        else if (g < 8)      { dst = g_kh + ((size_t)(bt*Hc + g))*Lc*HD; gmul = 1.0f; }
        else                 { dst = g_vh + ((size_t)(bt*Hc + g - 8))*Lc*HD;
                               gmul = g_gw[bt*Hc + g - 8]; }
        #pragma unroll
        for (int i = 0; i < 2; ++i) {
            float ss0 = 0.f, ss1 = 0.f;
            #pragma unroll
            for (int j = 0; j < 8; ++j) {
                float v0 = acc[i][j][0] + bb0[j], v1 = acc[i][j][1] + bb1[j];
                float v2 = acc[i][j][2] + bb0[j], v3 = acc[i][j][3] + bb1[j];
                ss0 += v0*v0 + v1*v1;
                ss1 += v2*v2 + v3*v3;
            }
            ss0 += __shfl_xor_sync(0xffffffffu, ss0, 1);
            ss0 += __shfl_xor_sync(0xffffffffu, ss0, 2);
            ss1 += __shfl_xor_sync(0xffffffffu, ss1, 1);
            ss1 += __shfl_xor_sync(0xffffffffu, ss1, 2);
            float inv0 = gmul / fmaxf(sqrtf(ss0), 1e-12f);
            float inv1 = gmul / fmaxf(sqrtf(ss1), 1e-12f);
            int l = m0 + wm + i*16 + row;
            uint32_t* p0 = (uint32_t*)(dst + (size_t)l*HD);
            uint32_t* p1 = (uint32_t*)(dst + (size_t)(l+8)*HD);
            #pragma unroll
            for (int j = 0; j < 8; ++j) {
                int dw = j*4 + (lane & 3);
                p0[dw] = packbf((acc[i][j][0]+bb0[j])*inv0, (acc[i][j][1]+bb1[j])*inv0);
                p1[dw] = packbf((acc[i][j][2]+bb0[j])*inv1, (acc[i][j][3]+bb1[j])*inv1);
            }
        }
    } else {
        // fused residual + transpose epilogue: out[b][n][t][m] = acc+bias+x
        for (int p = 0; p < 4; ++p) {
            __syncthreads();
            if ((wid & 3) == p) {
                #pragma unroll
                for (int i = 0; i < 2; ++i) {
                    #pragma unroll
                    for (int j = 0; j < 8; ++j) {
                        int n  = wn + j*8 + col;
                        int ml = i*16 + row;
                        float b0 = bias[n0+n], b1 = bias[n0+n+1];
                        stage[n*36 + ml]         = acc[i][j][0] + b0;
                        stage[(n+1)*36 + ml]     = acc[i][j][1] + b1;
                        stage[n*36 + ml + 8]     = acc[i][j][2] + b0;
                        stage[(n+1)*36 + ml + 8] = acc[i][j][3] + b1;
                    }
                }
            }
            __syncthreads();
            #pragma unroll
            for (int i = 0; i < 4; ++i) {
                int n  = r8 + i*32;
                int mm = (tid & 7) * 4;
                size_t gidx = (size_t)b*CTL + (size_t)(n0+n)*TL
                            + (size_t)t*Lc + m0 + p*32 + mm;
                float4 xv = *(const float4*)(src + gidx);
                float4 pv = *(float4*)&stage[n*36 + mm];
                *(float4*)&outp[gidx] =
                    make_float4(pv.x+xv.x, pv.y+xv.y, pv.z+xv.z, pv.w+xv.w);
            }
        }
    }
}

// ---------------- flash attention: double-buffered KV, no max-tracking ------
// |logit| <= 0.125 (q,k unit-normalized, scale folded) => exp never overflows.
__global__ void __launch_bounds__(256) k_attn() {
    extern __shared__ __align__(16) char asmem[];
    unsigned short* sq  = (unsigned short*)asmem;            // 128*72
    unsigned short* skb = (unsigned short*)(asmem + 18432);  // [2][64*72]
    uint32_t*       svp = (uint32_t*)(asmem + 36864);        // [2][64*36]

    int l0 = blockIdx.x * 128;
    int h  = blockIdx.y;
    int bt = blockIdx.z;
    int tid = threadIdx.x, lane = tid & 31, w = tid >> 5;
    const unsigned short* qp = g_qh + ((size_t)(bt*Hc+h)*Lc + l0)*HD;
    const unsigned short* kp = g_kh + ((size_t)(bt*Hc+h)*Lc)*HD;
    const unsigned short* vp = g_vh + ((size_t)(bt*Hc+h)*Lc)*HD;

    for (int i = tid; i < 1024; i += 256) {
        int r = i >> 3, d0 = (i & 7) * 8;
        *(uint4*)&sq[r*72 + d0] = *(const uint4*)(qp + (size_t)r*HD + d0);
    }

    uint32_t aQ = smem_u32(sq) + ((((w*16 + (lane & 15))*36) + ((lane >> 4) << 2)) << 2);
    uint32_t aK = smem_u32(skb) + ((((lane & 7) + ((lane >> 4) << 3))*36
                                   + (((lane >> 3) & 1) << 2)) << 2);
    uint32_t svb = smem_u32(svp);
    int rVbase = (lane & 7) + ((lane >> 4) << 3);
    int csHalf = (lane >> 3) & 1;

    // per-thread KV loader indices
    int kr0 = tid >> 3, kr1 = (tid + 256) >> 3;    // K rows (0..31, 32..63)
    int kd0 = (tid & 7) * 8;
    int kvp = tid >> 3;                             // V pair index 0..31
    int vcolw = ((((kvp >> 2) ^ (tid & 7)) << 2) | (kvp & 3));

    uint4 kr[2], vr[2];
    // load tile 0
    kr[0] = *(const uint4*)(kp + (size_t)kr0*HD + kd0);
    kr[1] = *(const uint4*)(kp + (size_t)kr1*HD + kd0);
    vr[0] = *(const uint4*)(vp + (size_t)(2*kvp)*HD + kd0);
    vr[1] = *(const uint4*)(vp + (size_t)(2*kvp + 1)*HD + kd0);
    // store tile 0 -> buffer 0
    {
        *(uint4*)&skb[kr0*72 + kd0] = kr[0];
        *(uint4*)&skb[kr1*72 + kd0] = kr[1];
        const unsigned short* a = (const unsigned short*)&vr[0];
        const unsigned short* b = (const unsigned short*)&vr[1];
        #pragma unroll
        for (int j = 0; j < 8; ++j)
            svp[(kd0+j)*36 + vcolw] = (uint32_t)a[j] | ((uint32_t)b[j] << 16);
    }
    // prefetch tile 1
    kr[0] = *(const uint4*)(kp + (size_t)(64 + kr0)*HD + kd0);
    kr[1] = *(const uint4*)(kp + (size_t)(64 + kr1)*HD + kd0);
    vr[0] = *(const uint4*)(vp + (size_t)(64 + 2*kvp)*HD + kd0);
    vr[1] = *(const uint4*)(vp + (size_t)(64 + 2*kvp + 1)*HD + kd0);

    float ls0 = 0.f, ls1 = 0.f;
    float o[8][4] = {};
    __syncthreads();

    for (int it = 0; it < 8; ++it) {
        int cur = it & 1, nxt = cur ^ 1;
        if (it < 7) {
            // store tile it+1 (in regs) -> buffer nxt
            unsigned short* kb = skb + nxt*4608;     // 64*72 ushorts
            uint32_t*       vb = svp + nxt*2304;     // 64*36 words
            *(uint4*)&kb[kr0*72 + kd0] = kr[0];
            *(uint4*)&kb[kr1*72 + kd0] = kr[1];
            const unsigned short* a = (const unsigned short*)&vr[0];
            const unsigned short* b = (const unsigned short*)&vr[1];
            #pragma unroll
            for (int j = 0; j < 8; ++j)
                vb[(kd0+j)*36 + vcolw] = (uint32_t)a[j] | ((uint32_t)b[j] << 16);
        }
        if (it < 6) {
            int jn = (it + 2) * 64;
            kr[0] = *(const uint4*)(kp + (size_t)(jn + kr0)*HD + kd0);
            kr[1] = *(const uint4*)(kp + (size_t)(jn + kr1)*HD + kd0);
            vr[0] = *(const uint4*)(vp + (size_t)(jn + 2*kvp)*HD + kd0);
            vr[1] = *(const uint4*)(vp + (size_t)(jn + 2*kvp + 1)*HD + kd0);
        }

        uint32_t bofK = cur * 9216;      // bytes
        uint32_t bofV = cur * 9216;

        // S = Q K^T
        float s[8][4] = {};
        #pragma unroll
        for (int ks = 0; ks < 4; ++ks) {
            uint32_t A[4];
            ldsm4(A, aQ + ((ks*8) << 2));
            #pragma unroll
            for (int jp = 0; jp < 4; ++jp) {
                uint32_t bb[4];
                ldsm4(bb, aK + bofK + ((jp*16*36 + ks*8) << 2));
                mma_bf16(s[2*jp],   A, bb[0], bb[1]);
                mma_bf16(s[2*jp+1], A, bb[2], bb[3]);
            }
        }

        // plain exp
        #pragma unroll
        for (int n = 0; n < 8; ++n) {
            s[n][0] = __expf(s[n][0]);
            s[n][1] = __expf(s[n][1]);
            s[n][2] = __expf(s[n][2]);
            s[n][3] = __expf(s[n][3]);
            ls0 += s[n][0] + s[n][1];
            ls1 += s[n][2] + s[n][3];
        }

        // O += P V
        #pragma unroll
        for (int kv = 0; kv < 4; ++kv) {
            uint32_t A[4];
            A[0] = packbf(s[2*kv][0],   s[2*kv][1]);
            A[1] = packbf(s[2*kv][2],   s[2*kv][3]);
            A[2] = packbf(s[2*kv+1][0], s[2*kv+1][1]);
            A[3] = packbf(s[2*kv+1][2], s[2*kv+1][3]);
            #pragma unroll
            for (int dp = 0; dp < 4; ++dp) {
                int r = dp*16 + rVbase;
                int cs = kv*2 + csHalf;
                uint32_t bb[4];
                ldsm4(bb, svb + bofV + ((r*36 + ((cs ^ (r >> 3)) << 2)) << 2));
                mma_bf16(o[2*dp],   A, bb[0], bb[1]);
                mma_bf16(o[2*dp+1], A, bb[2], bb[3]);
            }
        }
        __syncthreads();
    }

    // single final row-sum reduction across the lane quad
    ls0 += __shfl_xor_sync(0xffffffffu, ls0, 1);
    ls0 += __shfl_xor_sync(0xffffffffu, ls0, 2);
    ls1 += __shfl_xor_sync(0xffffffffu, ls1, 1);
    ls1 += __shfl_xor_sync(0xffffffffu, ls1, 2);

    // epilogue -> bf16 g_oh
    float gwv = g_gw[bt*Hc + h];
    float i0 = gwv / ls0, i1 = gwv / ls1;
    int qr = w*16 + (lane >> 2);
    int grow = bt*Lc + l0 + qr;
    uint32_t* ow = (uint32_t*)g_oh;
    int base0 = grow*(Cc/2) + h*(HD/2) + (lane & 3);
    int base1 = (grow+8)*(Cc/2) + h*(HD/2) + (lane & 3);
    #pragma unroll
    for (int d = 0; d < 8; ++d) {
        ow[base0 + d*4] = packbf(o[d][0]*i0, o[d][1]*i0);
        ow[base1 + d*4] = packbf(o[d][2]*i1, o[d][3]*i1);
    }
}

// ---------------- launcher: Q GEMM || (gate chain -> KV GEMM) ---------------
extern "C" void kernel_launch(void* const* d_in, const int* in_sizes, int n_in,
                              void* d_out, int out_size) {
    const float* e   = (const float*)d_in[0];
    const float* x   = (const float*)d_in[1];
    const float* Wq  = (const float*)d_in[2];
    const float* bq  = (const float*)d_in[3];
    const float* Wkv = (const float*)d_in[4];
    const float* bkv = (const float*)d_in[5];
    const float* Wm  = (const float*)d_in[6];
    const float* bm  = (const float*)d_in[7];
    const float* Wg1 = (const float*)d_in[8];
    const float* bg1 = (const float*)d_in[9];
    const float* Wg2 = (const float*)d_in[10];
    const float* bg2 = (const float*)d_in[11];
    float* out = (float*)d_out;

    static cudaStream_t s2 = nullptr;
    static cudaEvent_t evFork = nullptr, evJoin = nullptr;
    if (!s2) {
        cudaStreamCreateWithFlags(&s2, cudaStreamNonBlocking);
        cudaEventCreateWithFlags(&evFork, cudaEventDisableTiming);
        cudaEventCreateWithFlags(&evJoin, cudaEventDisableTiming);
        cudaFuncSetAttribute(k_attn,
            cudaFuncAttributeMaxDynamicSharedMemorySize, ATTN_SMEM);
    }

    // fork: gate chain + KV GEMM on side stream; Q GEMM on main stream
    cudaEventRecord(evFork, 0);
    cudaStreamWaitEvent(s2, evFork, 0);
    k_pool <<< (BT*Cc*32 + 255)/256, 256, 0, s2 >>>(e);
    k_gate1<<< dim3(4, BT), 256, 0, s2 >>>(Wg1, bg1);
    k_gate2<<< BT, 256, 0, s2 >>>(Wg2, bg2);
    k_gemm_bf16<<<dim3(8, 4, BT), 256, 0, s2>>>(1, Wkv, bkv, x, nullptr); // KV
    cudaEventRecord(evJoin, s2);

    k_gemm_bf16<<<dim3(4, 4, BT), 256>>>(0, Wq,  bq,  e, nullptr);   // Q + q-norm

    cudaStreamWaitEvent(0, evJoin, 0);
    k_attn<<<dim3(Lc/128, Hc, BT), 256, ATTN_SMEM>>>();
    k_gemm_bf16<<<dim3(4, 4, BT), 256>>>(2, Wm, bm, x, out);         // proj + resid
}

// round 16
// speedup vs baseline: 1.0357x; 1.0357x over previous
#include <cuda_runtime.h>
#include <cuda_bf16.h>
#include <math.h>
#include <stdint.h>

#define Bc 4
#define Cc 512
#define Tc 8
#define Lc 512
#define Hc 8
#define HD 64
#define BT 32               // B*T
#define CTL (Cc*Tc*Lc)
#define TL  (Tc*Lc)
#define SAP 20              // GEMM smem word pitch for row-major bf16x2 tiles
#define XP  68              // K-major A tile word pitch (conflict-free trans-LDSM)
#define BSTR 2560           // B buffer stride (words)  = 128*SAP
#define XSTR 2176           // X buffer stride (words)  = 32*XP
#define ASTR 2560           // A buffer stride (words)
#define ATTN_SMEM 55296     // 18432 (Q) + 2*9216 (K) + 2*9216 (V^T)

// ---------------- scratch (device globals; no allocation allowed) ----------
__device__ __align__(16) float g_pooled[BT*Cc];
__device__ __align__(16) float g_h1   [BT*Cc];
__device__ __align__(16) float g_gw   [BT*Hc];
__device__ __align__(16) unsigned short g_qh[(size_t)BT*Hc*Lc*HD];  // bf16, 0.125 folded
__device__ __align__(16) unsigned short g_kh[(size_t)BT*Hc*Lc*HD];  // bf16
__device__ __align__(16) unsigned short g_vh[(size_t)BT*Hc*Lc*HD];  // bf16 (no gw)
__device__ __align__(16) unsigned short g_oh[(size_t)BT*Lc*Cc];     // bf16 attn out

// ---------------- helpers ---------------------------------------------------
__device__ __forceinline__ void mma_bf16(float c[4], const uint32_t a[4],
                                         uint32_t b0, uint32_t b1) {
    asm volatile(
        "mma.sync.aligned.m16n8k16.row.col.f32.bf16.bf16.f32 "
        "{%0,%1,%2,%3},{%4,%5,%6,%7},{%8,%9},{%0,%1,%2,%3};"
        : "+f"(c[0]), "+f"(c[1]), "+f"(c[2]), "+f"(c[3])
        : "r"(a[0]), "r"(a[1]), "r"(a[2]), "r"(a[3]), "r"(b0), "r"(b1));
}
__device__ __forceinline__ uint32_t packbf(float lo, float hi) {
    uint32_t r;
    asm("cvt.rn.bf16x2.f32 %0, %1, %2;" : "=r"(r) : "f"(hi), "f"(lo));
    return r;
}
__device__ __forceinline__ void ldsm4(uint32_t a[4], uint32_t addr) {
    asm volatile("ldmatrix.sync.aligned.m8n8.x4.shared.b16 {%0,%1,%2,%3}, [%4];"
        : "=r"(a[0]), "=r"(a[1]), "=r"(a[2]), "=r"(a[3]) : "r"(addr));
}
__device__ __forceinline__ void ldsm4t(uint32_t a[4], uint32_t addr) {
    asm volatile("ldmatrix.sync.aligned.m8n8.x4.trans.shared.b16 {%0,%1,%2,%3}, [%4];"
        : "=r"(a[0]), "=r"(a[1]), "=r"(a[2]), "=r"(a[3]) : "r"(addr));
}
__device__ __forceinline__ uint32_t smem_u32(const void* p) {
    return (uint32_t)__cvta_generic_to_shared(p);
}

// ---------------- pooled[bt,c] = mean_l e[b,c,t,l] --------------------------
__global__ void k_pool(const float* __restrict__ e) {
    int w    = (blockIdx.x * blockDim.x + threadIdx.x) >> 5;
    int lane = threadIdx.x & 31;
    if (w >= BT*Cc) return;
    int bt = w / Cc, c = w % Cc;
    int b = bt / Tc, t = bt % Tc;
    const float* p = e + (size_t)b*CTL + (size_t)c*TL + (size_t)t*Lc;
    float s = 0.f;
    #pragma unroll 4
    for (int l = lane; l < Lc; l += 32) s += p[l];
    #pragma unroll
    for (int o = 16; o; o >>= 1) s += __shfl_xor_sync(0xffffffffu, s, o);
    if (!lane) g_pooled[w] = s * (1.0f/Lc);
}

// ---------------- gate layer 1 ---------------------------------------------
__global__ void __launch_bounds__(256) k_gate1(
        const float* __restrict__ Wg1, const float* __restrict__ bg1) {
    __shared__ float sp[Cc];
    int bt = blockIdx.y;
    int r0 = blockIdx.x * 128;
    int tid = threadIdx.x, warp = tid >> 5, lane = tid & 31;
    sp[tid] = g_pooled[bt*Cc + tid];
    sp[tid+256] = g_pooled[bt*Cc + tid + 256];
    __syncthreads();
    const float4* pp = (const float4*)sp;
    #pragma unroll
    for (int i = 0; i < 16; ++i) {
        int r = r0 + warp*16 + i;
        const float4* wr = (const float4*)(Wg1 + (size_t)r*Cc);
        float a = 0.f;
        #pragma unroll
        for (int k = lane; k < Cc/4; k += 32) {
            float4 wv = wr[k]; float4 pv = pp[k];
            a += wv.x*pv.x + wv.y*pv.y + wv.z*pv.z + wv.w*pv.w;
        }
        #pragma unroll
        for (int o = 16; o; o >>= 1) a += __shfl_xor_sync(0xffffffffu, a, o);
        if (!lane) g_h1[bt*Cc + r] = tanhf(a + bg1[r]);
    }
}

// ---------------- gate layer 2 + softmax ------------------------------------
__global__ void __launch_bounds__(256) k_gate2(
        const float* __restrict__ Wg2, const float* __restrict__ bg2) {
    __shared__ float sg[Hc];
    int bt = blockIdx.x;
    int tid = threadIdx.x, warp = tid >> 5, lane = tid & 31;
    if (warp < Hc) {
        const float4* w2 = (const float4*)(Wg2 + (size_t)warp*Cc);
        const float4* hp = (const float4*)(g_h1 + bt*Cc);
        float a = 0.f;
        #pragma unroll
        for (int k = lane; k < Cc/4; k += 32) {
            float4 wv = w2[k]; float4 hv = hp[k];
            a += wv.x*hv.x + wv.y*hv.y + wv.z*hv.z + wv.w*hv.w;
        }
        #pragma unroll
        for (int o = 16; o; o >>= 1) a += __shfl_xor_sync(0xffffffffu, a, o);
        if (!lane) sg[warp] = a + bg2[warp];
    }
    __syncthreads();
    if (tid == 0) {
        float mx = sg[0];
        #pragma unroll
        for (int h = 1; h < Hc; ++h) mx = fmaxf(mx, sg[h]);
        float ex[Hc], ssum = 0.f;
        #pragma unroll
        for (int h = 0; h < Hc; ++h) { ex[h] = expf(sg[h]-mx); ssum += ex[h]; }
        #pragma unroll
        for (int h = 0; h < Hc; ++h) g_gw[bt*Hc+h] = ex[h]/ssum;
    }
}

// ---------------- bf16 tensor-core GEMM (double-buffered smem) --------------
// mode 0: merged Q+KV. blockIdx.x<4 -> Q (A=e), else KV (A=x). grid (12,4,BT)
//         fused norm epilogues -> g_qh / g_kh / g_vh (v WITHOUT gw; gw^2 in attn)
// mode 2: A = g_oh, W=Wm, fused residual+transpose -> out. grid (4,4,BT)
__global__ void __launch_bounds__(256, 2) k_gemm_bf16(int mode,
        const float* __restrict__ Wq, const float* __restrict__ Wkv,
        const float* __restrict__ Wm,
        const float* __restrict__ bq, const float* __restrict__ bkv,
        const float* __restrict__ bm,
        const float* __restrict__ e, const float* __restrict__ x,
        float* __restrict__ outp) {
    __shared__ __align__(16) uint32_t smw[10240];       // 40960 bytes
    uint32_t* sBw = smw;                                // [2][128*SAP]
    uint32_t* sXw = smw + 2*BSTR;                       // [2][32*XP]   (which<2)
    uint32_t* sAw = smw + 2*BSTR;                       // [2][128*SAP] (which==2)
    float*    stage = (float*)smw;                      // epilogue alias (which==2)

    int bt = blockIdx.z;
    int b = bt / Tc, t = bt % Tc;
    int m0 = blockIdx.y * 128;
    int tid = threadIdx.x, lane = tid & 31, wid = tid >> 5;
    int wm = (wid & 3) * 32;
    int wn = (wid >> 2) * 64;
    int r8 = tid >> 3;            // 0..31
    int c8 = (tid & 7) * 4;

    int which, n0;
    const float* W; const float* bias; const float* src;
    if (mode == 2)            { which = 2; n0 = blockIdx.x * 128;       W = Wm;  bias = bm;  src = x; }
    else if (blockIdx.x < 4)  { which = 0; n0 = blockIdx.x * 128;       W = Wq;  bias = bq;  src = e; }
    else                      { which = 1; n0 = (blockIdx.x - 4) * 128; W = Wkv; bias = bkv; src = x; }

    const float* tb = src + (size_t)b*CTL + (size_t)t*Lc;       // which<2
    const uint32_t* Ao = (const uint32_t*)g_oh + (size_t)bt*Lc*(Cc/2); // which==2

    // LDSM base addresses (buffer 0)
    uint32_t adB = smem_u32(sBw) + ((((wn + (lane & 7) + ((lane >> 4) << 3))*SAP)
                                     + (((lane >> 3) & 1) << 2)) << 2);
    uint32_t adA = smem_u32(sAw) + ((((wm + (lane & 15))*SAP) + ((lane >> 4) << 2)) << 2);
    uint32_t adX = smem_u32(sXw)
        + ((((lane & 7) + ((lane >> 4) << 3))*XP + (wm >> 1) + (((lane >> 3) & 1) << 2)) << 2);

    float acc[2][8][4] = {};
    float4 pB[4];
    float4 pA[4];
    uint4  qA[2];

    // ---- load tile 0 into regs ----
    #pragma unroll
    for (int i = 0; i < 4; ++i)
        pB[i] = *(const float4*)(W + (size_t)(n0 + r8 + i*32)*Cc + c8);
    if (which == 2) {
        const uint32_t* ap = Ao + (size_t)(tid >> 1)*(Cc/2) + (tid & 1)*8;
        qA[0] = *(const uint4*)(ap);
        qA[1] = *(const uint4*)(ap + 4);
    } else {
        #pragma unroll
        for (int i = 0; i < 4; ++i)
            pA[i] = *(const float4*)(tb + (size_t)r8*TL + m0 + (tid & 7)*16 + 4*i);
    }
    // ---- store tile 0 -> buffer 0 ----
    #pragma unroll
    for (int i = 0; i < 4; ++i) {
        uint2 u = make_uint2(packbf(pB[i].x, pB[i].y), packbf(pB[i].z, pB[i].w));
        *(uint2*)&sBw[(r8 + i*32)*SAP + (c8 >> 1)] = u;
    }
    if (which == 2) {
        uint32_t* dp = &sAw[(tid >> 1)*SAP + (tid & 1)*8];
        *(uint4*)dp       = qA[0];
        *(uint4*)(dp + 4) = qA[1];
    } else {
        uint32_t* dp = &sXw[r8*XP + (tid & 7)*8];
        #pragma unroll
        for (int i = 0; i < 4; ++i)
            *(uint2*)(dp + 2*i) =
                make_uint2(packbf(pA[i].x, pA[i].y), packbf(pA[i].z, pA[i].w));
    }
    // ---- prefetch tile 1 into regs ----
    #pragma unroll
    for (int i = 0; i < 4; ++i)
        pB[i] = *(const float4*)(W + (size_t)(n0 + r8 + i*32)*Cc + 32 + c8);
    if (which == 2) {
        const uint32_t* ap = Ao + (size_t)(tid >> 1)*(Cc/2) + 16 + (tid & 1)*8;
        qA[0] = *(const uint4*)(ap);
        qA[1] = *(const uint4*)(ap + 4);
    } else {
        #pragma unroll
        for (int i = 0; i < 4; ++i)
            pA[i] = *(const float4*)(tb + (size_t)(32 + r8)*TL + m0 + (tid & 7)*16 + 4*i);
    }
    __syncthreads();

    // ---- main loop: 16 k-tiles, ping-pong, ONE sync per tile ----
    for (int kt = 0; kt < 16; ++kt) {
        int cur = kt & 1, nxt = cur ^ 1;
        if (kt < 15) {
            #pragma unroll
            for (int i = 0; i < 4; ++i) {
                uint2 u = make_uint2(packbf(pB[i].x, pB[i].y), packbf(pB[i].z, pB[i].w));
                *(uint2*)&sBw[nxt*BSTR + (r8 + i*32)*SAP + (c8 >> 1)] = u;
            }
            if (which == 2) {
                uint32_t* dp = &sAw[nxt*ASTR + (tid >> 1)*SAP + (tid & 1)*8];
                *(uint4*)dp       = qA[0];
                *(uint4*)(dp + 4) = qA[1];
            } else {
                uint32_t* dp = &sXw[nxt*XSTR + r8*XP + (tid & 7)*8];
                #pragma unroll
                for (int i = 0; i < 4; ++i)
                    *(uint2*)(dp + 2*i) =
                        make_uint2(packbf(pA[i].x, pA[i].y), packbf(pA[i].z, pA[i].w));
            }
        }
        if (kt < 14) {
            int kn = (kt + 2) * 32;
            #pragma unroll
            for (int i = 0; i < 4; ++i)
                pB[i] = *(const float4*)(W + (size_t)(n0 + r8 + i*32)*Cc + kn + c8);
            if (which == 2) {
                const uint32_t* ap = Ao + (size_t)(tid >> 1)*(Cc/2) + (kn >> 1) + (tid & 1)*8;
                qA[0] = *(const uint4*)(ap);
                qA[1] = *(const uint4*)(ap + 4);
            } else {
                #pragma unroll
                for (int i = 0; i < 4; ++i)
                    pA[i] = *(const float4*)(tb + (size_t)(kn + r8)*TL + m0 + (tid & 7)*16 + 4*i);
            }
        }
        uint32_t bofB = cur * (BSTR*4);
        uint32_t bofX = cur * (XSTR*4);
        #pragma unroll
        for (int ks = 0; ks < 2; ++ks) {
            uint32_t A0[4], A1[4];
            if (which == 2) {
                ldsm4(A0, adA + bofB + ((ks*8) << 2));
                ldsm4(A1, adA + bofB + ((16*SAP + ks*8) << 2));
            } else {
                ldsm4t(A0, adX + bofX + ((ks*16*XP) << 2));
                ldsm4t(A1, adX + bofX + ((ks*16*XP + 8) << 2));
            }
            #pragma unroll
            for (int jp = 0; jp < 4; ++jp) {
                uint32_t bb[4];
                ldsm4(bb, adB + bofB + ((jp*16*SAP + ks*8) << 2));
                mma_bf16(acc[0][2*jp],   A0, bb[0], bb[1]);
                mma_bf16(acc[1][2*jp],   A1, bb[0], bb[1]);
                mma_bf16(acc[0][2*jp+1], A0, bb[2], bb[3]);
                mma_bf16(acc[1][2*jp+1], A1, bb[2], bb[3]);
            }
        }
        __syncthreads();
    }

    int row = lane >> 2, col = (lane & 3) * 2;
    if (which < 2) {
        // fused normalization epilogue (head = 64 cols = one warp tile column)
        int g = (n0 + wn) >> 6;
        float bb0[8], bb1[8];
        #pragma unroll
        for (int j = 0; j < 8; ++j) {
            int gn = n0 + wn + j*8 + col;
            bb0[j] = bias[gn]; bb1[j] = bias[gn+1];
        }
        unsigned short* dst; float gmul;
        if (which == 0)      { dst = g_qh + ((size_t)(bt*Hc + g))*Lc*HD; gmul = 0.125f; }
        else if (g < 8)      { dst = g_kh + ((size_t)(bt*Hc + g))*Lc*HD; gmul = 1.0f; }
        else                 { dst = g_vh + ((size_t)(bt*Hc + g - 8))*Lc*HD; gmul = 1.0f; }
        #pragma unroll
        for (int i = 0; i < 2; ++i) {
            float ss0 = 0.f, ss1 = 0.f;
            #pragma unroll
            for (int j = 0; j < 8; ++j) {
                float v0 = acc[i][j][0] + bb0[j], v1 = acc[i][j][1] + bb1[j];
                float v2 = acc[i][j][2] + bb0[j], v3 = acc[i][j][3] + bb1[j];
                ss0 += v0*v0 + v1*v1;
                ss1 += v2*v2 + v3*v3;
            }
            ss0 += __shfl_xor_sync(0xffffffffu, ss0, 1);
            ss0 += __shfl_xor_sync(0xffffffffu, ss0, 2);
            ss1 += __shfl_xor_sync(0xffffffffu, ss1, 1);
            ss1 += __shfl_xor_sync(0xffffffffu, ss1, 2);
            float inv0 = gmul / fmaxf(sqrtf(ss0), 1e-12f);
            float inv1 = gmul / fmaxf(sqrtf(ss1), 1e-12f);
            int l = m0 + wm + i*16 + row;
            uint32_t* p0 = (uint32_t*)(dst + (size_t)l*HD);
            uint32_t* p1 = (uint32_t*)(dst + (size_t)(l+8)*HD);
            #pragma unroll
            for (int j = 0; j < 8; ++j) {
                int dw = j*4 + (lane & 3);
                p0[dw] = packbf((acc[i][j][0]+bb0[j])*inv0, (acc[i][j][1]+bb1[j])*inv0);
                p1[dw] = packbf((acc[i][j][2]+bb0[j])*inv1, (acc[i][j][3]+bb1[j])*inv1);
            }
        }
    } else {
        // fused residual + transpose epilogue: out[b][n][t][m] = acc+bias+x
        for (int p = 0; p < 4; ++p) {
            __syncthreads();
            if ((wid & 3) == p) {
                #pragma unroll
                for (int i = 0; i < 2; ++i) {
                    #pragma unroll
                    for (int j = 0; j < 8; ++j) {
                        int n  = wn + j*8 + col;
                        int ml = i*16 + row;
                        float b0 = bias[n0+n], b1 = bias[n0+n+1];
                        stage[n*36 + ml]         = acc[i][j][0] + b0;
                        stage[(n+1)*36 + ml]     = acc[i][j][1] + b1;
                        stage[n*36 + ml + 8]     = acc[i][j][2] + b0;
                        stage[(n+1)*36 + ml + 8] = acc[i][j][3] + b1;
                    }
                }
            }
            __syncthreads();
            #pragma unroll
            for (int i = 0; i < 4; ++i) {
                int n  = r8 + i*32;
                int mm = (tid & 7) * 4;
                size_t gidx = (size_t)b*CTL + (size_t)(n0+n)*TL
                            + (size_t)t*Lc + m0 + p*32 + mm;
                float4 xv = *(const float4*)(src + gidx);
                float4 pv = *(float4*)&stage[n*36 + mm];
                *(float4*)&outp[gidx] =
                    make_float4(pv.x+xv.x, pv.y+xv.y, pv.z+xv.z, pv.w+xv.w);
            }
        }
    }
}

// ---------------- flash attention: double-buffered KV, gw^2 epilogue --------
// |logit| <= 0.125 (q,k unit-normalized, scale folded) => exp never overflows.
__global__ void __launch_bounds__(256) k_attn() {
    extern __shared__ __align__(16) char asmem[];
    unsigned short* sq  = (unsigned short*)asmem;            // 128*72
    unsigned short* skb = (unsigned short*)(asmem + 18432);  // [2][64*72]
    uint32_t*       svp = (uint32_t*)(asmem + 36864);        // [2][64*36]

    int l0 = blockIdx.x * 128;
    int h  = blockIdx.y;
    int bt = blockIdx.z;
    int tid = threadIdx.x, lane = tid & 31, w = tid >> 5;
    const unsigned short* qp = g_qh + ((size_t)(bt*Hc+h)*Lc + l0)*HD;
    const unsigned short* kp = g_kh + ((size_t)(bt*Hc+h)*Lc)*HD;
    const unsigned short* vp = g_vh + ((size_t)(bt*Hc+h)*Lc)*HD;

    for (int i = tid; i < 1024; i += 256) {
        int r = i >> 3, d0 = (i & 7) * 8;
        *(uint4*)&sq[r*72 + d0] = *(const uint4*)(qp + (size_t)r*HD + d0);
    }

    uint32_t aQ = smem_u32(sq) + ((((w*16 + (lane & 15))*36) + ((lane >> 4) << 2)) << 2);
    uint32_t aK = smem_u32(skb) + ((((lane & 7) + ((lane >> 4) << 3))*36
                                   + (((lane >> 3) & 1) << 2)) << 2);
    uint32_t svb = smem_u32(svp);
    int rVbase = (lane & 7) + ((lane >> 4) << 3);
    int csHalf = (lane >> 3) & 1;

    int kr0 = tid >> 3, kr1 = (tid + 256) >> 3;
    int kd0 = (tid & 7) * 8;
    int kvp = tid >> 3;
    int vcolw = ((((kvp >> 2) ^ (tid & 7)) << 2) | (kvp & 3));

    uint4 kr[2], vr[2];
    kr[0] = *(const uint4*)(kp + (size_t)kr0*HD + kd0);
    kr[1] = *(const uint4*)(kp + (size_t)kr1*HD + kd0);
    vr[0] = *(const uint4*)(vp + (size_t)(2*kvp)*HD + kd0);
    vr[1] = *(const uint4*)(vp + (size_t)(2*kvp + 1)*HD + kd0);
    {
        *(uint4*)&skb[kr0*72 + kd0] = kr[0];
        *(uint4*)&skb[kr1*72 + kd0] = kr[1];
        const unsigned short* a = (const unsigned short*)&vr[0];
        const unsigned short* b = (const unsigned short*)&vr[1];
        #pragma unroll
        for (int j = 0; j < 8; ++j)
            svp[(kd0+j)*36 + vcolw] = (uint32_t)a[j] | ((uint32_t)b[j] << 16);
    }
    kr[0] = *(const uint4*)(kp + (size_t)(64 + kr0)*HD + kd0);
    kr[1] = *(const uint4*)(kp + (size_t)(64 + kr1)*HD + kd0);
    vr[0] = *(const uint4*)(vp + (size_t)(64 + 2*kvp)*HD + kd0);
    vr[1] = *(const uint4*)(vp + (size_t)(64 + 2*kvp + 1)*HD + kd0);

    float ls0 = 0.f, ls1 = 0.f;
    float o[8][4] = {};
    __syncthreads();

    for (int it = 0; it < 8; ++it) {
        int cur = it & 1, nxt = cur ^ 1;
        if (it < 7) {
            unsigned short* kb = skb + nxt*4608;
            uint32_t*       vb = svp + nxt*2304;
            *(uint4*)&kb[kr0*72 + kd0] = kr[0];
            *(uint4*)&kb[kr1*72 + kd0] = kr[1];
            const unsigned short* a = (const unsigned short*)&vr[0];
            const unsigned short* b = (const unsigned short*)&vr[1];
            #pragma unroll
            for (int j = 0; j < 8; ++j)
                vb[(kd0+j)*36 + vcolw] = (uint32_t)a[j] | ((uint32_t)b[j] << 16);
        }
        if (it < 6) {
            int jn = (it + 2) * 64;
            kr[0] = *(const uint4*)(kp + (size_t)(jn + kr0)*HD + kd0);
            kr[1] = *(const uint4*)(kp + (size_t)(jn + kr1)*HD + kd0);
            vr[0] = *(const uint4*)(vp + (size_t)(jn + 2*kvp)*HD + kd0);
            vr[1] = *(const uint4*)(vp + (size_t)(jn + 2*kvp + 1)*HD + kd0);
        }

        uint32_t bofK = cur * 9216;
        uint32_t bofV = cur * 9216;

        float s[8][4] = {};
        #pragma unroll
        for (int ks = 0; ks < 4; ++ks) {
            uint32_t A[4];
            ldsm4(A, aQ + ((ks*8) << 2));
            #pragma unroll
            for (int jp = 0; jp < 4; ++jp) {
                uint32_t bb[4];
                ldsm4(bb, aK + bofK + ((jp*16*36 + ks*8) << 2));
                mma_bf16(s[2*jp],   A, bb[0], bb[1]);
                mma_bf16(s[2*jp+1], A, bb[2], bb[3]);
            }
        }
        #pragma unroll
        for (int n = 0; n < 8; ++n) {
            s[n][0] = __expf(s[n][0]);
            s[n][1] = __expf(s[n][1]);
            s[n][2] = __expf(s[n][2]);
            s[n][3] = __expf(s[n][3]);
            ls0 += s[n][0] + s[n][1];
            ls1 += s[n][2] + s[n][3];
        }
        #pragma unroll
        for (int kv = 0; kv < 4; ++kv) {
            uint32_t A[4];
            A[0] = packbf(s[2*kv][0],   s[2*kv][1]);
            A[1] = packbf(s[2*kv][2],   s[2*kv][3]);
            A[2] = packbf(s[2*kv+1][0], s[2*kv+1][1]);
            A[3] = packbf(s[2*kv+1][2], s[2*kv+1][3]);
            #pragma unroll
            for (int dp = 0; dp < 4; ++dp) {
                int r = dp*16 + rVbase;
                int cs = kv*2 + csHalf;
                uint32_t bb[4];
                ldsm4(bb, svb + bofV + ((r*36 + ((cs ^ (r >> 3)) << 2)) << 2));
                mma_bf16(o[2*dp],   A, bb[0], bb[1]);
                mma_bf16(o[2*dp+1], A, bb[2], bb[3]);
            }
        }
        __syncthreads();
    }

    ls0 += __shfl_xor_sync(0xffffffffu, ls0, 1);
    ls0 += __shfl_xor_sync(0xffffffffu, ls0, 2);
    ls1 += __shfl_xor_sync(0xffffffffu, ls1, 1);
    ls1 += __shfl_xor_sync(0xffffffffu, ls1, 2);

    // epilogue -> bf16 g_oh, gw^2 fold (v-side gw + output-side gw)
    float gwv = g_gw[bt*Hc + h];
    float gw2 = gwv * gwv;
    float i0 = gw2 / ls0, i1 = gw2 / ls1;
    int qr = w*16 + (lane >> 2);
    int grow = bt*Lc + l0 + qr;
    uint32_t* ow = (uint32_t*)g_oh;
    int base0 = grow*(Cc/2) + h*(HD/2) + (lane & 3);
    int base1 = (grow+8)*(Cc/2) + h*(HD/2) + (lane & 3);
    #pragma unroll
    for (int d = 0; d < 8; ++d) {
        ow[base0 + d*4] = packbf(o[d][0]*i0, o[d][1]*i0);
        ow[base1 + d*4] = packbf(o[d][2]*i1, o[d][3]*i1);
    }
}

// ---------------- launcher: merged QKV GEMM || gate chain -------------------
extern "C" void kernel_launch(void* const* d_in, const int* in_sizes, int n_in,
                              void* d_out, int out_size) {
    const float* e   = (const float*)d_in[0];
    const float* x   = (const float*)d_in[1];
    const float* Wq  = (const float*)d_in[2];
    const float* bq  = (const float*)d_in[3];
    const float* Wkv = (const float*)d_in[4];
    const float* bkv = (const float*)d_in[5];
    const float* Wm  = (const float*)d_in[6];
    const float* bm  = (const float*)d_in[7];
    const float* Wg1 = (const float*)d_in[8];
    const float* bg1 = (const float*)d_in[9];
    const float* Wg2 = (const float*)d_in[10];
    const float* bg2 = (const float*)d_in[11];
    float* out = (float*)d_out;

    static cudaStream_t s2 = nullptr;
    static cudaEvent_t evFork = nullptr, evJoin = nullptr;
    if (!s2) {
        cudaStreamCreateWithFlags(&s2, cudaStreamNonBlocking);
        cudaEventCreateWithFlags(&evFork, cudaEventDisableTiming);
        cudaEventCreateWithFlags(&evJoin, cudaEventDisableTiming);
        cudaFuncSetAttribute(k_attn,
            cudaFuncAttributeMaxDynamicSharedMemorySize, ATTN_SMEM);
    }

    // fork: gate chain on side stream (needed only by attention's gw^2)
    cudaEventRecord(evFork, 0);
    cudaStreamWaitEvent(s2, evFork, 0);
    k_pool <<< (BT*Cc*32 + 255)/256, 256, 0, s2 >>>(e);
    k_gate1<<< dim3(4, BT), 256, 0, s2 >>>(Wg1, bg1);
    k_gate2<<< BT, 256, 0, s2 >>>(Wg2, bg2);
    cudaEventRecord(evJoin, s2);

    // merged Q + KV GEMM (single launch, single tail wave)
    k_gemm_bf16<<<dim3(12, 4, BT), 256>>>(0, Wq, Wkv, Wm, bq, bkv, bm, e, x, nullptr);

    cudaStreamWaitEvent(0, evJoin, 0);
    k_attn<<<dim3(Lc/128, Hc, BT), 256, ATTN_SMEM>>>();
    k_gemm_bf16<<<dim3(4, 4, BT), 256>>>(2, Wq, Wkv, Wm, bq, bkv, bm, e, x, out);
}